// round 2
// baseline (speedup 1.0000x reference)
#include <cuda_runtime.h>
#include <cuda_bf16.h>
#include <mma.h>

using namespace nvcuda;

#define NROWS 8192
#define DIM   1024
#define INV_T 10.0f

// ---------------- scratch (device globals; no allocation) ----------------
__device__ __nv_bfloat16 g_imn[NROWS * DIM];   // 16 MB
__device__ __nv_bfloat16 g_capn[NROWS * DIM];  // 16 MB
__device__ float g_rowsum[NROWS];
__device__ float g_colsum[NROWS];
__device__ float g_diag[NROWS];

// ---------------- 1) normalize rows, write bf16 ----------------
__global__ void normalize_kernel(const float* __restrict__ im,
                                 const float* __restrict__ cap) {
    int row = blockIdx.x;
    const float* src = (blockIdx.y == 0) ? im : cap;
    __nv_bfloat16* dst = (blockIdx.y == 0) ? g_imn : g_capn;

    const float4* src4 = reinterpret_cast<const float4*>(src + (size_t)row * DIM);
    float4 v = src4[threadIdx.x];           // 256 threads * 4 = 1024
    float ss = v.x * v.x + v.y * v.y + v.z * v.z + v.w * v.w;

    #pragma unroll
    for (int o = 16; o; o >>= 1) ss += __shfl_xor_sync(0xffffffffu, ss, o);

    __shared__ float wss[8];
    if ((threadIdx.x & 31) == 0) wss[threadIdx.x >> 5] = ss;
    __syncthreads();
    float total = 0.f;
    #pragma unroll
    for (int i = 0; i < 8; i++) total += wss[i];

    float inv = rsqrtf(total);
    __nv_bfloat162* d2 = reinterpret_cast<__nv_bfloat162*>(dst + (size_t)row * DIM);
    d2[threadIdx.x * 2 + 0] = __floats2bfloat162_rn(v.x * inv, v.y * inv);
    d2[threadIdx.x * 2 + 1] = __floats2bfloat162_rn(v.z * inv, v.w * inv);
}

// ---------------- 2) zero accumulators ----------------
__global__ void zero_kernel() {
    int i = blockIdx.x * blockDim.x + threadIdx.x;
    if (i < NROWS) {
        g_rowsum[i] = 0.f;
        g_colsum[i] = 0.f;
        g_diag[i]   = 0.f;
    }
}

// ---------------- 3) fused GEMM + exp + row/col reduction ----------------
// Block tile 128x128, 8 warps (2x4), warp tile 64x32 = 4x2 wmma 16x16x16 frags.
#define BM 128
#define BN 128
#define BK 16
#define LDS_AB 24   // bf16 smem leading dim (48B rows, mult of 16B)
#define LDS_FB 20   // f32 fragment-buffer leading dim (80B, mult of 16B)

__global__ __launch_bounds__(256) void gemm_kernel() {
    __shared__ __align__(16) __nv_bfloat16 As[BM * LDS_AB];
    __shared__ __align__(16) __nv_bfloat16 Bs[BN * LDS_AB];
    __shared__ __align__(16) float fragbuf[8][16 * LDS_FB];
    __shared__ float rowsum_s[BM];
    __shared__ float colsum_s[BN];

    const int tid  = threadIdx.x;
    const int warp = tid >> 5;
    const int lane = tid & 31;
    const int warpM = warp >> 2;   // 0..1  -> 64-row slab
    const int warpN = warp & 3;    // 0..3  -> 32-col slab
    const int rowBase = blockIdx.y * BM;
    const int colBase = blockIdx.x * BN;

    if (tid < BM) rowsum_s[tid] = 0.f;
    else          colsum_s[tid - BM] = 0.f;

    wmma::fragment<wmma::accumulator, 16, 16, 16, float> acc[4][2];
    #pragma unroll
    for (int i = 0; i < 4; i++)
        #pragma unroll
        for (int j = 0; j < 2; j++)
            wmma::fill_fragment(acc[i][j], 0.0f);

    const int ldRow = tid >> 1;          // 0..127
    const int ldK   = (tid & 1) * 8;     // 0 or 8

    const size_t aBase = (size_t)(rowBase + ldRow) * DIM + ldK;
    const size_t bBase = (size_t)(colBase + ldRow) * DIM + ldK;

    for (int k0 = 0; k0 < DIM; k0 += BK) {
        uint4 a = *reinterpret_cast<const uint4*>(&g_imn[aBase + k0]);
        uint4 b = *reinterpret_cast<const uint4*>(&g_capn[bBase + k0]);
        __syncthreads();  // previous iteration's frag loads done
        *reinterpret_cast<uint4*>(&As[ldRow * LDS_AB + ldK]) = a;
        *reinterpret_cast<uint4*>(&Bs[ldRow * LDS_AB + ldK]) = b;
        __syncthreads();

        wmma::fragment<wmma::matrix_a, 16, 16, 16, __nv_bfloat16, wmma::row_major> af[4];
        wmma::fragment<wmma::matrix_b, 16, 16, 16, __nv_bfloat16, wmma::col_major> bf[2];
        #pragma unroll
        for (int i = 0; i < 4; i++)
            wmma::load_matrix_sync(af[i], &As[(warpM * 64 + i * 16) * LDS_AB], LDS_AB);
        #pragma unroll
        for (int j = 0; j < 2; j++)
            wmma::load_matrix_sync(bf[j], &Bs[(warpN * 32 + j * 16) * LDS_AB], LDS_AB);

        #pragma unroll
        for (int i = 0; i < 4; i++)
            #pragma unroll
            for (int j = 0; j < 2; j++)
                wmma::mma_sync(acc[i][j], af[i], bf[j], acc[i][j]);
    }

    // ---- epilogue: per-fragment exp + row/col partial sums ----
    float* fb = fragbuf[warp];
    #pragma unroll
    for (int i = 0; i < 4; i++) {
        #pragma unroll
        for (int j = 0; j < 2; j++) {
            wmma::store_matrix_sync(fb, acc[i][j], LDS_FB, wmma::mem_row_major);
            __syncwarp();

            const int giBase = rowBase + warpM * 64 + i * 16;
            const int gjBase = colBase + warpN * 32 + j * 16;

            // row pass: lane -> (r = lane&15, half = lane>>4 selects 8 cols)
            {
                int r = lane & 15;
                int half = lane >> 4;
                int gi = giBase + r;
                float s = 0.f;
                #pragma unroll
                for (int cc = 0; cc < 8; cc++) {
                    int c = half * 8 + cc;
                    float v = fb[r * LDS_FB + c] * INV_T;
                    if (gi == gjBase + c) g_diag[gi] = v;   // diagonal logit
                    float e = __expf(v);
                    fb[r * LDS_FB + c] = e;                 // reuse for col pass
                    s += e;
                }
                s += __shfl_down_sync(0xffffffffu, s, 16);
                if (half == 0) atomicAdd(&rowsum_s[warpM * 64 + i * 16 + r], s);
            }
            __syncwarp();

            // col pass: lane -> (c = lane&15, half selects 8 rows)
            {
                int c = lane & 15;
                int half = lane >> 4;
                float s = 0.f;
                #pragma unroll
                for (int rr = 0; rr < 8; rr++)
                    s += fb[(half * 8 + rr) * LDS_FB + c];
                s += __shfl_down_sync(0xffffffffu, s, 16);
                if (half == 0) atomicAdd(&colsum_s[warpN * 32 + j * 16 + c], s);
            }
            __syncwarp();
        }
    }

    __syncthreads();
    if (tid < BM) atomicAdd(&g_rowsum[rowBase + tid], rowsum_s[tid]);
    else          atomicAdd(&g_colsum[colBase + tid - BM], colsum_s[tid - BM]);
}

// ---------------- 4) finalize ----------------
__global__ void finalize_kernel(float* __restrict__ out) {
    int tid = threadIdx.x;
    float a = 0.f, d = 0.f;
    for (int i = tid; i < NROWS; i += 256) {
        a += logf(g_rowsum[i]) + logf(g_colsum[i]);
        d += g_diag[i];
    }
    #pragma unroll
    for (int o = 16; o; o >>= 1) {
        a += __shfl_xor_sync(0xffffffffu, a, o);
        d += __shfl_xor_sync(0xffffffffu, d, o);
    }
    __shared__ float sa[8], sd[8];
    if ((tid & 31) == 0) { sa[tid >> 5] = a; sd[tid >> 5] = d; }
    __syncthreads();
    if (tid == 0) {
        float ta = 0.f, td = 0.f;
        #pragma unroll
        for (int i = 0; i < 8; i++) { ta += sa[i]; td += sd[i]; }
        out[0] = 0.5f * ta / (float)NROWS - td / (float)NROWS;
    }
}

// ---------------- launch ----------------
extern "C" void kernel_launch(void* const* d_in, const int* in_sizes, int n_in,
                              void* d_out, int out_size) {
    const float* im  = (const float*)d_in[0];
    const float* cap = (const float*)d_in[1];
    float* out = (float*)d_out;

    normalize_kernel<<<dim3(NROWS, 2), 256>>>(im, cap);
    zero_kernel<<<(NROWS + 255) / 256, 256>>>();
    gemm_kernel<<<dim3(NROWS / BN, NROWS / BM), 256>>>();
    finalize_kernel<<<1, 256>>>(out);
}

// round 3
// speedup vs baseline: 1.0016x; 1.0016x over previous
#include <cuda_runtime.h>
#include <cuda_bf16.h>
#include <mma.h>

using namespace nvcuda;

#define NROWS 8192
#define DIM   1024
#define INV_T 10.0f

// ---------------- scratch (device globals; no allocation) ----------------
__device__ __nv_bfloat16 g_imn[NROWS * DIM];   // 16 MB
__device__ __nv_bfloat16 g_capn[NROWS * DIM];  // 16 MB
__device__ float g_rowsum[NROWS];
__device__ float g_colsum[NROWS];
__device__ float g_diag[NROWS];

// ---------------- 1) normalize rows, write bf16 ----------------
__global__ void normalize_kernel(const float* __restrict__ im,
                                 const float* __restrict__ cap) {
    int row = blockIdx.x;
    const float* src = (blockIdx.y == 0) ? im : cap;
    __nv_bfloat16* dst = (blockIdx.y == 0) ? g_imn : g_capn;

    const float4* src4 = reinterpret_cast<const float4*>(src + (size_t)row * DIM);
    float4 v = src4[threadIdx.x];           // 256 threads * 4 = 1024
    float ss = v.x * v.x + v.y * v.y + v.z * v.z + v.w * v.w;

    #pragma unroll
    for (int o = 16; o; o >>= 1) ss += __shfl_xor_sync(0xffffffffu, ss, o);

    __shared__ float wss[8];
    if ((threadIdx.x & 31) == 0) wss[threadIdx.x >> 5] = ss;
    __syncthreads();
    float total = 0.f;
    #pragma unroll
    for (int i = 0; i < 8; i++) total += wss[i];

    float inv = rsqrtf(total);
    __nv_bfloat162* d2 = reinterpret_cast<__nv_bfloat162*>(dst + (size_t)row * DIM);
    d2[threadIdx.x * 2 + 0] = __floats2bfloat162_rn(v.x * inv, v.y * inv);
    d2[threadIdx.x * 2 + 1] = __floats2bfloat162_rn(v.z * inv, v.w * inv);
}

// ---------------- 2) zero accumulators ----------------
__global__ void zero_kernel() {
    int i = blockIdx.x * blockDim.x + threadIdx.x;
    if (i < NROWS) {
        g_rowsum[i] = 0.f;
        g_colsum[i] = 0.f;
        g_diag[i]   = 0.f;
    }
}

// ---------------- 3) fused GEMM + exp + row/col reduction ----------------
// Block tile 128x128, 8 warps (2x4), warp tile 64x32 = 4x2 wmma 16x16x16 frags.
#define BM 128
#define BN 128
#define BK 16
#define LDS_AB 24   // bf16 smem leading dim (48B rows, mult of 16B)
#define LDS_FB 20   // f32 fragment-buffer leading dim (80B, mult of 16B)

__global__ __launch_bounds__(256) void gemm_kernel() {
    __shared__ __align__(16) __nv_bfloat16 As[BM * LDS_AB];
    __shared__ __align__(16) __nv_bfloat16 Bs[BN * LDS_AB];
    __shared__ __align__(16) float fragbuf[8][16 * LDS_FB];
    __shared__ float rowsum_s[BM];
    __shared__ float colsum_s[BN];

    const int tid  = threadIdx.x;
    const int warp = tid >> 5;
    const int lane = tid & 31;
    const int warpM = warp >> 2;   // 0..1  -> 64-row slab
    const int warpN = warp & 3;    // 0..3  -> 32-col slab
    const int rowBase = blockIdx.y * BM;
    const int colBase = blockIdx.x * BN;

    if (tid < BM) rowsum_s[tid] = 0.f;
    else          colsum_s[tid - BM] = 0.f;

    wmma::fragment<wmma::accumulator, 16, 16, 16, float> acc[4][2];
    #pragma unroll
    for (int i = 0; i < 4; i++)
        #pragma unroll
        for (int j = 0; j < 2; j++)
            wmma::fill_fragment(acc[i][j], 0.0f);

    const int ldRow = tid >> 1;          // 0..127
    const int ldK   = (tid & 1) * 8;     // 0 or 8

    const size_t aBase = (size_t)(rowBase + ldRow) * DIM + ldK;
    const size_t bBase = (size_t)(colBase + ldRow) * DIM + ldK;

    for (int k0 = 0; k0 < DIM; k0 += BK) {
        uint4 a = *reinterpret_cast<const uint4*>(&g_imn[aBase + k0]);
        uint4 b = *reinterpret_cast<const uint4*>(&g_capn[bBase + k0]);
        __syncthreads();  // previous iteration's frag loads done
        *reinterpret_cast<uint4*>(&As[ldRow * LDS_AB + ldK]) = a;
        *reinterpret_cast<uint4*>(&Bs[ldRow * LDS_AB + ldK]) = b;
        __syncthreads();

        wmma::fragment<wmma::matrix_a, 16, 16, 16, __nv_bfloat16, wmma::row_major> af[4];
        wmma::fragment<wmma::matrix_b, 16, 16, 16, __nv_bfloat16, wmma::col_major> bf[2];
        #pragma unroll
        for (int i = 0; i < 4; i++)
            wmma::load_matrix_sync(af[i], &As[(warpM * 64 + i * 16) * LDS_AB], LDS_AB);
        #pragma unroll
        for (int j = 0; j < 2; j++)
            wmma::load_matrix_sync(bf[j], &Bs[(warpN * 32 + j * 16) * LDS_AB], LDS_AB);

        #pragma unroll
        for (int i = 0; i < 4; i++)
            #pragma unroll
            for (int j = 0; j < 2; j++)
                wmma::mma_sync(acc[i][j], af[i], bf[j], acc[i][j]);
    }

    // ---- epilogue: per-fragment exp + row/col partial sums ----
    float* fb = fragbuf[warp];
    #pragma unroll
    for (int i = 0; i < 4; i++) {
        #pragma unroll
        for (int j = 0; j < 2; j++) {
            wmma::store_matrix_sync(fb, acc[i][j], LDS_FB, wmma::mem_row_major);
            __syncwarp();

            const int giBase = rowBase + warpM * 64 + i * 16;
            const int gjBase = colBase + warpN * 32 + j * 16;

            // row pass: lane -> (r = lane&15, half = lane>>4 selects 8 cols)
            {
                int r = lane & 15;
                int half = lane >> 4;
                int gi = giBase + r;
                float s = 0.f;
                #pragma unroll
                for (int cc = 0; cc < 8; cc++) {
                    int c = half * 8 + cc;
                    float v = fb[r * LDS_FB + c] * INV_T;
                    if (gi == gjBase + c) g_diag[gi] = v;   // diagonal logit
                    float e = __expf(v);
                    fb[r * LDS_FB + c] = e;                 // reuse for col pass
                    s += e;
                }
                s += __shfl_down_sync(0xffffffffu, s, 16);
                if (half == 0) atomicAdd(&rowsum_s[warpM * 64 + i * 16 + r], s);
            }
            __syncwarp();

            // col pass: lane -> (c = lane&15, half selects 8 rows)
            {
                int c = lane & 15;
                int half = lane >> 4;
                float s = 0.f;
                #pragma unroll
                for (int rr = 0; rr < 8; rr++)
                    s += fb[(half * 8 + rr) * LDS_FB + c];
                s += __shfl_down_sync(0xffffffffu, s, 16);
                if (half == 0) atomicAdd(&colsum_s[warpN * 32 + j * 16 + c], s);
            }
            __syncwarp();
        }
    }

    __syncthreads();
    if (tid < BM) atomicAdd(&g_rowsum[rowBase + tid], rowsum_s[tid]);
    else          atomicAdd(&g_colsum[colBase + tid - BM], colsum_s[tid - BM]);
}

// ---------------- 4) finalize ----------------
__global__ void finalize_kernel(float* __restrict__ out) {
    int tid = threadIdx.x;
    float a = 0.f, d = 0.f;
    for (int i = tid; i < NROWS; i += 256) {
        a += logf(g_rowsum[i]) + logf(g_colsum[i]);
        d += g_diag[i];
    }
    #pragma unroll
    for (int o = 16; o; o >>= 1) {
        a += __shfl_xor_sync(0xffffffffu, a, o);
        d += __shfl_xor_sync(0xffffffffu, d, o);
    }
    __shared__ float sa[8], sd[8];
    if ((tid & 31) == 0) { sa[tid >> 5] = a; sd[tid >> 5] = d; }
    __syncthreads();
    if (tid == 0) {
        float ta = 0.f, td = 0.f;
        #pragma unroll
        for (int i = 0; i < 8; i++) { ta += sa[i]; td += sd[i]; }
        out[0] = 0.5f * ta / (float)NROWS - td / (float)NROWS;
    }
}

// ---------------- launch ----------------
extern "C" void kernel_launch(void* const* d_in, const int* in_sizes, int n_in,
                              void* d_out, int out_size) {
    const float* im  = (const float*)d_in[0];
    const float* cap = (const float*)d_in[1];
    float* out = (float*)d_out;

    normalize_kernel<<<dim3(NROWS, 2), 256>>>(im, cap);
    zero_kernel<<<(NROWS + 255) / 256, 256>>>();
    gemm_kernel<<<dim3(NROWS / BN, NROWS / BM), 256>>>();
    finalize_kernel<<<1, 256>>>(out);
}